// round 12
// baseline (speedup 1.0000x reference)
#include <cuda_runtime.h>
#include <cuda_fp16.h>
#include <math.h>
#include <stdint.h>

#define SEQ    1024
#define DIMM   1024
#define NHEADS 16
#define FFD    4096
#define NBATCH 2
#define NTOK   (NBATCH*SEQ)
#define NDEPTH 6

// ---------------- scratch (allocation-free: __device__ globals) ----------------
__device__ __half g_hh[NTOK*DIMM];
__device__ __half g_qkvh[NTOK*3*DIMM];
__device__ __half g_oh[NTOK*DIMM];
__device__ __half g_ffh[NTOK*FFD];
__device__ __half g_wqkvh[(size_t)NDEPTH*DIMM*3*DIMM];
__device__ __half g_wouth[(size_t)NDEPTH*DIMM*DIMM];
__device__ __half g_w1h[(size_t)NDEPTH*DIMM*FFD];
__device__ __half g_w2h[(size_t)NDEPTH*FFD*DIMM];
__device__ __half g_rpbh[(size_t)NHEADS*SEQ*SEQ];

// ---------------- ptx helpers ----------------
__device__ __forceinline__ uint32_t smem_u32(const void* p){
  uint32_t a;
  asm("{ .reg .u64 t; cvta.to.shared.u64 t, %1; cvt.u32.u64 %0, t; }" : "=r"(a) : "l"(p));
  return a;
}
__device__ __forceinline__ void mma16h(float* d, const uint32_t* a, const uint32_t* b){
  asm volatile("mma.sync.aligned.m16n8k16.row.col.f32.f16.f16.f32 "
    "{%0,%1,%2,%3}, {%4,%5,%6,%7}, {%8,%9}, {%0,%1,%2,%3};\n"
    : "+f"(d[0]),"+f"(d[1]),"+f"(d[2]),"+f"(d[3])
    : "r"(a[0]),"r"(a[1]),"r"(a[2]),"r"(a[3]),
      "r"(b[0]),"r"(b[1]));
}
__device__ __forceinline__ void ldm_x4(uint32_t* r, uint32_t addr){
  asm volatile("ldmatrix.sync.aligned.m8n8.x4.shared.b16 {%0,%1,%2,%3}, [%4];"
    : "=r"(r[0]),"=r"(r[1]),"=r"(r[2]),"=r"(r[3]) : "r"(addr));
}
__device__ __forceinline__ void ldm_x4t(uint32_t* r, uint32_t addr){
  asm volatile("ldmatrix.sync.aligned.m8n8.x4.trans.shared.b16 {%0,%1,%2,%3}, [%4];"
    : "=r"(r[0]),"=r"(r[1]),"=r"(r[2]),"=r"(r[3]) : "r"(addr));
}
__device__ __forceinline__ void cp16(uint32_t smem, const void* g){
  asm volatile("cp.async.cg.shared.global [%0], [%1], 16;" :: "r"(smem), "l"(g));
}
#define CP_COMMIT() asm volatile("cp.async.commit_group;" ::: "memory")
#define CP_WAIT0()  asm volatile("cp.async.wait_group 0;" ::: "memory")
#define CP_WAIT1()  asm volatile("cp.async.wait_group 1;" ::: "memory")
#define CP_WAIT2()  asm volatile("cp.async.wait_group 2;" ::: "memory")

__device__ __forceinline__ uint32_t packh2(float x, float y){
  __half2 h = __floats2half2_rn(x, y);
  return *(uint32_t*)&h;
}

// ---------------- fused 2-value block reduction (blockDim.x == 256) ----------------
__device__ __forceinline__ float2 blockReduceSum2(float2 v, float2* sh){
  #pragma unroll
  for(int o=16;o>0;o>>=1){
    v.x += __shfl_xor_sync(0xffffffffu, v.x, o);
    v.y += __shfl_xor_sync(0xffffffffu, v.y, o);
  }
  int wid = threadIdx.x>>5;
  __syncthreads();
  if((threadIdx.x&31)==0) sh[wid]=v;
  __syncthreads();
  float2 r = sh[0];
  #pragma unroll
  for(int w=1;w<8;w++){ r.x += sh[w].x; r.y += sh[w].y; }
  return r;
}

// ---------------- merged fp32->fp16 conversion (single launch) ----------------
#define CN1 (NDEPTH*DIMM*3*DIMM/4)
#define CN2 (NDEPTH*DIMM*DIMM/4)
#define CN3 (NDEPTH*DIMM*FFD/4)
#define CN4 (NDEPTH*FFD*DIMM/4)
#define CN5 (NHEADS*SEQ*SEQ/4)
#define CNT (CN1+CN2+CN3+CN4+CN5)

__global__ void conv_all(const float* __restrict__ wq, const float* __restrict__ wo,
                         const float* __restrict__ w1, const float* __restrict__ w2,
                         const float* __restrict__ rp,
                         __half* __restrict__ dq, __half* __restrict__ dо_,
                         __half* __restrict__ d1, __half* __restrict__ d2,
                         __half* __restrict__ dr){
  int i = blockIdx.x*blockDim.x + threadIdx.x;
  const float* src; __half* dst; int off;
  if(i < CN1){ src=wq; dst=dq; off=i; }
  else if(i < CN1+CN2){ src=wo; dst=dо_; off=i-CN1; }
  else if(i < CN1+CN2+CN3){ src=w1; dst=d1; off=i-(CN1+CN2); }
  else if(i < CN1+CN2+CN3+CN4){ src=w2; dst=d2; off=i-(CN1+CN2+CN3); }
  else if(i < CNT){ src=rp; dst=dr; off=i-(CN1+CN2+CN3+CN4); }
  else return;
  float4 v = ((const float4*)src)[off];
  uint2 u;
  u.x = packh2(v.x, v.y);
  u.y = packh2(v.z, v.w);
  ((uint2*)dst)[off] = u;
}

// LayerNorm with single fused reduction pass (sum + sumsq together)
__global__ void layernorm_h(const float* __restrict__ x, const float* __restrict__ g,
                            const float* __restrict__ beta, __half* __restrict__ out){
  __shared__ float2 sh[8];
  int row = blockIdx.x, t = threadIdx.x;
  const float4* xr = (const float4*)(x + (size_t)row*DIMM);
  float4 v = xr[t];
  float2 acc;
  acc.x = v.x+v.y+v.z+v.w;
  acc.y = v.x*v.x + v.y*v.y + v.z*v.z + v.w*v.w;
  acc = blockReduceSum2(acc, sh);
  float mu = acc.x * (1.f/DIMM);
  float var = acc.y * (1.f/DIMM) - mu*mu;
  float rinv = rsqrtf(var + 1e-5f);
  const float4 gg = ((const float4*)g)[t];
  const float4 bb = ((const float4*)beta)[t];
  uint2 u;
  u.x = packh2((v.x-mu)*rinv*gg.x + bb.x, (v.y-mu)*rinv*gg.y + bb.y);
  u.y = packh2((v.z-mu)*rinv*gg.z + bb.z, (v.w-mu)*rinv*gg.w + bb.w);
  ((uint2*)(out + (size_t)row*DIMM))[t] = u;
}

// ---------------- fp16 GEMM: cp.async 4-stage pipeline, templated M-tile ----------------
#define APITCH 40
#define BPITCH 136
#define BSZ (32*BPITCH)
#define GH_SMEM_OF(BM) (4*((BM)*APITCH + BSZ)*2)

template<int EPI, typename OT, int BM>
__global__ void __launch_bounds__(256)
gemm_h(const __half* __restrict__ A, int lda,
       const __half* __restrict__ B, int ldb,
       OT* __restrict__ C, int ldc,
       const float* __restrict__ bias, const float* __restrict__ res,
       int M, int N, int K)
{
  constexpr int MT = BM/32;
  constexpr int NT = 4;
  constexpr int ASZ = BM*APITCH;
  constexpr int STG = ASZ+BSZ;
  constexpr int AIT = BM/64;
  extern __shared__ __half smh[];

  int t=threadIdx.x;
  const __half* Ag = A + (size_t)blockIdx.y*BM*lda;
  const __half* Bg = B + blockIdx.x*128;

  float acc[MT][NT][4];
  #pragma unroll
  for(int i=0;i<MT;i++)
    #pragma unroll
    for(int j=0;j<NT;j++)
      #pragma unroll
      for(int r=0;r<4;r++) acc[i][j][r]=0.f;

  int wid=t>>5, lane=t&31;
  int wm=wid>>2, wn=wid&3;
  int m0=wm*(16*MT), n0=wn*32;
  int qr=lane>>2, rr=lane&3;

  uint32_t sbase = smem_u32(smh);
  uint32_t aoff = sbase + (uint32_t)(((m0 + (lane&15))*APITCH + (lane>>4)*8) * 2);
  uint32_t boff = sbase + (uint32_t)((ASZ + (lane&15)*BPITCH + n0 + (lane>>4)*8) * 2);

  const int KT = K >> 5;

  auto load_tile = [&](int kt, int buf){
    __half* As = smh + buf*STG;
    __half* Bs = As + ASZ;
    const __half* Asrc = Ag + kt*32;
    #pragma unroll
    for(int i=0;i<AIT;i++){
      int c=t+256*i;
      cp16(smem_u32(As + (c>>2)*APITCH + ((c&3)<<3)),
           Asrc + (size_t)(c>>2)*lda + ((c&3)<<3));
    }
    const __half* Bsrc = Bg + (size_t)(kt*32)*ldb;
    #pragma unroll
    for(int i=0;i<2;i++){
      int c=t+256*i;
      cp16(smem_u32(Bs + (c>>4)*BPITCH + ((c&15)<<3)),
           Bsrc + (size_t)(c>>4)*ldb + ((c&15)<<3));
    }
  };

  #pragma unroll
  for(int s=0;s<3;s++){ load_tile(s,s); CP_COMMIT(); }

  for(int kt=0;kt<KT;kt++){
    CP_WAIT2();
    __syncthreads();
    if(kt+3<KT) load_tile(kt+3,(kt+3)&3);
    CP_COMMIT();
    uint32_t so = (uint32_t)(((kt&3)*STG)*2);
    #pragma unroll
    for(int ks=0;ks<2;ks++){
      uint32_t af[MT][4];
      #pragma unroll
      for(int mt=0;mt<MT;mt++)
        ldm_x4(af[mt], aoff + so + (uint32_t)((mt*16*APITCH + ks*16)*2));
      uint32_t bf[2][4];
      #pragma unroll
      for(int nh=0;nh<2;nh++)
        ldm_x4t(bf[nh], boff + so + (uint32_t)((ks*16*BPITCH + nh*16)*2));
      #pragma unroll
      for(int mt=0;mt<MT;mt++)
        #pragma unroll
        for(int nt=0;nt<NT;nt++)
          mma16h(acc[mt][nt], af[mt], &bf[nt>>1][(nt&1)*2]);
    }
  }

  int brow = blockIdx.y*BM + m0 + qr;
  int bcol = blockIdx.x*128 + n0 + (rr<<1);
  #pragma unroll
  for(int mt=0;mt<MT;mt++){
    #pragma unroll
    for(int nt=0;nt<NT;nt++){
      int col = bcol + nt*8;
      #pragma unroll
      for(int hh=0;hh<2;hh++){
        int row = brow + mt*16 + hh*8;
        float vx = acc[mt][nt][2*hh+0];
        float vy = acc[mt][nt][2*hh+1];
        if(EPI==1||EPI==2){ vx += bias[col]; vy += bias[col+1]; }
        if(EPI==2){
          vx = 0.5f*vx*(1.f+erff(vx*0.70710678118654752f));
          vy = 0.5f*vy*(1.f+erff(vy*0.70710678118654752f));
        }
        if(EPI==1){
          vx += res[(size_t)row*ldc+col];
          vy += res[(size_t)row*ldc+col+1];
        }
        if(sizeof(OT)==2){
          *(uint32_t*)((__half*)C + (size_t)row*ldc + col) = packh2(vx,vy);
        }else{
          float2 o; o.x=vx; o.y=vy;
          *(float2*)((float*)C + (size_t)row*ldc + col) = o;
        }
      }
    }
  }
}

// ---------------- fused flash attention: 128 Q rows / block (8 warps) ----------------
// K/V tiles amortized over 2x the Q rows vs R11 (halves K/V gmem+smem traffic).
// Per-warp math identical to the R8/R11 measured-best version.
#define FPITCH 72

__global__ void __launch_bounds__(256)
attn_flash_h(const __half* __restrict__ qkv, const __half* __restrict__ rpb,
             __half* __restrict__ O)
{
  __shared__ __half Qs[128*FPITCH];
  __shared__ __half Ks[2*64*FPITCH];
  __shared__ __half Vs[2*64*FPITCH];

  int t = threadIdx.x, lane = t&31, w = t>>5;   // 8 warps
  int qr = lane>>2, rr = lane&3;
  int it = blockIdx.x, bh = blockIdx.y;
  int b = bh>>4, h = bh&15;
  const __half* Qg = qkv + (size_t)(b*SEQ + it*128)*(3*DIMM) + h*64;
  const __half* Kg = qkv + (size_t)b*SEQ*(3*DIMM) + DIMM   + h*64;
  const __half* Vg = qkv + (size_t)b*SEQ*(3*DIMM) + 2*DIMM + h*64;

  uint32_t sQ = smem_u32(Qs), sK = smem_u32(Ks), sV = smem_u32(Vs);

  // Q: 128 rows x 64 halves = 1024 cp16s / 256 threads = 4 each
  #pragma unroll
  for(int u=0;u<4;u++){
    int c = t + 256*u;
    int row = c>>3, cc = c&7;
    cp16(sQ + (uint32_t)(row*FPITCH + cc*8)*2, Qg + (size_t)row*(3*DIMM) + cc*8);
  }
  // K+V tile 0 then tile 1: each 2*512 cp16s / 256 threads = 4 each
  #pragma unroll
  for(int u=0;u<4;u++){
    int c = t + 256*u;
    int mat = c>>9, row=(c>>3)&63, cc=c&7;
    const __half* src = (mat? Vg:Kg) + (size_t)row*(3*DIMM) + cc*8;
    uint32_t dst = (mat? sV:sK) + (uint32_t)(row*FPITCH + cc*8)*2;
    cp16(dst, src);
  }
  CP_COMMIT();
  #pragma unroll
  for(int u=0;u<4;u++){
    int c = t + 256*u;
    int mat = c>>9, row=(c>>3)&63, cc=c&7;
    const __half* src = (mat? Vg:Kg) + (size_t)(64+row)*(3*DIMM) + cc*8;
    uint32_t dst = (mat? sV:sK) + (uint32_t)(64*FPITCH + row*FPITCH + cc*8)*2;
    cp16(dst, src);
  }
  CP_COMMIT();

  int m0 = w*16;                               // warp's 16-row slice of 128
  const __half* Rg = rpb + ((size_t)h*SEQ + it*128 + m0 + qr)*SEQ + 2*rr;

  uint32_t a_base  = sQ + (uint32_t)(((m0 + (lane&15))*FPITCH + (lane>>4)*8)*2);
  uint32_t k_lbase = (uint32_t)((((lane&7) + ((lane&16)?8:0))*FPITCH + ((lane&8)?8:0))*2);
  uint32_t v_lbase = (uint32_t)(((lane&15)*FPITCH + (lane>>4)*8)*2);

  uint32_t qf[4][4];
  float oacc[8][4];
  #pragma unroll
  for(int nf=0;nf<8;nf++)
    #pragma unroll
    for(int r=0;r<4;r++) oacc[nf][r]=0.f;
  float mrow0=-1e30f, mrow1=-1e30f, lrow0=0.f, lrow1=0.f;

  for(int jt=0;jt<16;jt++){
    if(jt<15) CP_WAIT1(); else CP_WAIT0();
    __syncthreads();
    if(jt==0){
      #pragma unroll
      for(int kb=0;kb<4;kb++) ldm_x4(qf[kb], a_base + (uint32_t)(kb*16*2));
    }
    uint32_t bufK = sK + (uint32_t)((jt&1)*64*FPITCH*2);
    uint32_t bufV = sV + (uint32_t)((jt&1)*64*FPITCH*2);

    uint32_t rpf[8][2];
    {
      const __half* rp = Rg + jt*64;
      #pragma unroll
      for(int nf=0;nf<8;nf++){
        rpf[nf][0] = *(const uint32_t*)(rp + nf*8);
        rpf[nf][1] = *(const uint32_t*)(rp + 8*SEQ + nf*8);
      }
    }

    float s[8][4];
    #pragma unroll
    for(int nf=0;nf<8;nf++)
      #pragma unroll
      for(int r=0;r<4;r++) s[nf][r]=0.f;
    #pragma unroll
    for(int kb=0;kb<4;kb++){
      #pragma unroll
      for(int jnp=0;jnp<4;jnp++){
        uint32_t kr[4];
        ldm_x4(kr, bufK + k_lbase + (uint32_t)((jnp*16*FPITCH + kb*16)*2));
        mma16h(s[2*jnp  ], qf[kb], kr);
        mma16h(s[2*jnp+1], qf[kb], kr+2);
      }
    }
    #pragma unroll
    for(int nf=0;nf<8;nf++){
      float2 r0 = __half22float2(*(__half2*)&rpf[nf][0]);
      float2 r1 = __half22float2(*(__half2*)&rpf[nf][1]);
      s[nf][0]=fmaf(s[nf][0],0.125f,r0.x);
      s[nf][1]=fmaf(s[nf][1],0.125f,r0.y);
      s[nf][2]=fmaf(s[nf][2],0.125f,r1.x);
      s[nf][3]=fmaf(s[nf][3],0.125f,r1.y);
    }
    float mx0=-1e30f, mx1=-1e30f;
    #pragma unroll
    for(int nf=0;nf<8;nf++){
      mx0=fmaxf(mx0,fmaxf(s[nf][0],s[nf][1]));
      mx1=fmaxf(mx1,fmaxf(s[nf][2],s[nf][3]));
    }
    mx0=fmaxf(mx0,__shfl_xor_sync(0xffffffffu,mx0,1));
    mx0=fmaxf(mx0,__shfl_xor_sync(0xffffffffu,mx0,2));
    mx1=fmaxf(mx1,__shfl_xor_sync(0xffffffffu,mx1,1));
    mx1=fmaxf(mx1,__shfl_xor_sync(0xffffffffu,mx1,2));
    float mn0=fmaxf(mrow0,mx0), mn1=fmaxf(mrow1,mx1);
    float a0=__expf(mrow0-mn0), a1=__expf(mrow1-mn1);
    mrow0=mn0; mrow1=mn1;
    float sum0=0.f, sum1=0.f;
    #pragma unroll
    for(int nf=0;nf<8;nf++){
      s[nf][0]=__expf(s[nf][0]-mn0); s[nf][1]=__expf(s[nf][1]-mn0);
      s[nf][2]=__expf(s[nf][2]-mn1); s[nf][3]=__expf(s[nf][3]-mn1);
      sum0 += s[nf][0]+s[nf][1];
      sum1 += s[nf][2]+s[nf][3];
    }
    sum0 += __shfl_xor_sync(0xffffffffu,sum0,1);
    sum0 += __shfl_xor_sync(0xffffffffu,sum0,2);
    sum1 += __shfl_xor_sync(0xffffffffu,sum1,1);
    sum1 += __shfl_xor_sync(0xffffffffu,sum1,2);
    lrow0 = lrow0*a0 + sum0;
    lrow1 = lrow1*a1 + sum1;
    #pragma unroll
    for(int nf=0;nf<8;nf++){
      oacc[nf][0]*=a0; oacc[nf][1]*=a0;
      oacc[nf][2]*=a1; oacc[nf][3]*=a1;
    }
    uint32_t pf[4][4];
    #pragma unroll
    for(int kb=0;kb<4;kb++){
      pf[kb][0]=packh2(s[2*kb  ][0], s[2*kb  ][1]);
      pf[kb][1]=packh2(s[2*kb  ][2], s[2*kb  ][3]);
      pf[kb][2]=packh2(s[2*kb+1][0], s[2*kb+1][1]);
      pf[kb][3]=packh2(s[2*kb+1][2], s[2*kb+1][3]);
    }
    #pragma unroll
    for(int kb=0;kb<4;kb++){
      #pragma unroll
      for(int nfp=0;nfp<4;nfp++){
        uint32_t vr[4];
        ldm_x4t(vr, bufV + v_lbase + (uint32_t)((kb*16*FPITCH + nfp*16)*2));
        mma16h(oacc[2*nfp  ], pf[kb], vr);
        mma16h(oacc[2*nfp+1], pf[kb], vr+2);
      }
    }
    __syncthreads();
    if(jt<14){
      int nt = jt+2, buf = jt&1;
      #pragma unroll
      for(int u=0;u<4;u++){
        int c = t + 256*u;
        int mat = c>>9, row=(c>>3)&63, cc=c&7;
        const __half* src = (mat? Vg:Kg) + (size_t)(nt*64+row)*(3*DIMM) + cc*8;
        uint32_t dst = (mat? sV:sK) + (uint32_t)(buf*64*FPITCH + row*FPITCH + cc*8)*2;
        cp16(dst, src);
      }
      CP_COMMIT();
    }
  }

  float inv0=1.f/lrow0, inv1=1.f/lrow1;
  __half* Ob = O + (size_t)(b*SEQ + it*128)*DIMM + h*64;
  #pragma unroll
  for(int nf=0;nf<8;nf++){
    *(uint32_t*)(Ob + (size_t)(m0+qr  )*DIMM + nf*8+2*rr) = packh2(oacc[nf][0]*inv0, oacc[nf][1]*inv0);
    *(uint32_t*)(Ob + (size_t)(m0+qr+8)*DIMM + nf*8+2*rr) = packh2(oacc[nf][2]*inv1, oacc[nf][3]*inv1);
  }
}

// ---------------- driver ----------------
extern "C" void kernel_launch(void* const* d_in, const int* in_sizes, int n_in,
                              void* d_out, int out_size){
  const float* x     =(const float*)d_in[0];
  const float* rpb   =(const float*)d_in[1];
  const float* ln1_g =(const float*)d_in[2];
  const float* ln1_b =(const float*)d_in[3];
  const float* w_qkv =(const float*)d_in[4];
  const float* w_out =(const float*)d_in[5];
  const float* b_out =(const float*)d_in[6];
  const float* ln2_g =(const float*)d_in[7];
  const float* ln2_b =(const float*)d_in[8];
  const float* w1    =(const float*)d_in[9];
  const float* b1    =(const float*)d_in[10];
  const float* w2    =(const float*)d_in[11];
  const float* b2    =(const float*)d_in[12];
  float* X = (float*)d_out;

  __half *hh, *qkvh, *oh, *ffh, *wqkvh, *wouth, *w1h, *w2h, *rpbh;
  cudaGetSymbolAddress((void**)&hh,    g_hh);
  cudaGetSymbolAddress((void**)&qkvh,  g_qkvh);
  cudaGetSymbolAddress((void**)&oh,    g_oh);
  cudaGetSymbolAddress((void**)&ffh,   g_ffh);
  cudaGetSymbolAddress((void**)&wqkvh, g_wqkvh);
  cudaGetSymbolAddress((void**)&wouth, g_wouth);
  cudaGetSymbolAddress((void**)&w1h,   g_w1h);
  cudaGetSymbolAddress((void**)&w2h,   g_w2h);
  cudaGetSymbolAddress((void**)&rpbh,  g_rpbh);

  cudaFuncSetAttribute((const void*)gemm_h<0,__half,128>, cudaFuncAttributeMaxDynamicSharedMemorySize, GH_SMEM_OF(128));
  cudaFuncSetAttribute((const void*)gemm_h<2,__half,128>, cudaFuncAttributeMaxDynamicSharedMemorySize, GH_SMEM_OF(128));
  cudaFuncSetAttribute((const void*)gemm_h<1,float,64>,   cudaFuncAttributeMaxDynamicSharedMemorySize, GH_SMEM_OF(64));

  conv_all<<<(CNT+255)/256, 256>>>(w_qkv, w_out, w1, w2, rpb,
                                   wqkvh, wouth, w1h, w2h, rpbh);

  for(int l=0;l<NDEPTH;l++){
    const float* Xin = (l==0) ? x : X;
    // ---- attention block ----
    layernorm_h<<<NTOK,256>>>(Xin, ln1_g + l*DIMM, ln1_b + l*DIMM, hh);
    gemm_h<0,__half,128><<<dim3(24,16),256,GH_SMEM_OF(128)>>>(
        hh, DIMM, wqkvh + (size_t)l*DIMM*3*DIMM, 3*DIMM,
        qkvh, 3*DIMM, nullptr, nullptr, NTOK, 3*DIMM, DIMM);
    attn_flash_h<<<dim3(8,NBATCH*NHEADS),256>>>(qkvh, rpbh, oh);
    gemm_h<1,float,64><<<dim3(8,32),256,GH_SMEM_OF(64)>>>(
        oh, DIMM, wouth + (size_t)l*DIMM*DIMM, DIMM,
        X, DIMM, b_out + l*DIMM, Xin, NTOK, DIMM, DIMM);
    // ---- FFN block ----
    layernorm_h<<<NTOK,256>>>(X, ln2_g + l*DIMM, ln2_b + l*DIMM, hh);
    gemm_h<2,__half,128><<<dim3(32,16),256,GH_SMEM_OF(128)>>>(
        hh, DIMM, w1h + (size_t)l*DIMM*FFD, FFD,
        ffh, FFD, b1 + l*FFD, nullptr, NTOK, FFD, DIMM);
    gemm_h<1,float,64><<<dim3(8,32),256,GH_SMEM_OF(64)>>>(
        ffh, FFD, w2h + (size_t)l*FFD*DIMM, DIMM,
        X, DIMM, b2 + l*DIMM, X, NTOK, DIMM, FFD);
  }
}

// round 13
// speedup vs baseline: 1.0036x; 1.0036x over previous
#include <cuda_runtime.h>
#include <cuda_fp16.h>
#include <math.h>
#include <stdint.h>

#define SEQ    1024
#define DIMM   1024
#define NHEADS 16
#define FFD    4096
#define NBATCH 2
#define NTOK   (NBATCH*SEQ)
#define NDEPTH 6

// ---------------- scratch (allocation-free: __device__ globals) ----------------
__device__ __half g_hh[NTOK*DIMM];
__device__ __half g_qkvh[NTOK*3*DIMM];
__device__ __half g_oh[NTOK*DIMM];
__device__ __half g_ffh[NTOK*FFD];
__device__ __half g_wqkvh[(size_t)NDEPTH*DIMM*3*DIMM];
__device__ __half g_wouth[(size_t)NDEPTH*DIMM*DIMM];
__device__ __half g_w1h[(size_t)NDEPTH*DIMM*FFD];
__device__ __half g_w2h[(size_t)NDEPTH*FFD*DIMM];
__device__ __half g_rpbh[(size_t)NHEADS*SEQ*SEQ];

// ---------------- ptx helpers ----------------
__device__ __forceinline__ uint32_t smem_u32(const void* p){
  uint32_t a;
  asm("{ .reg .u64 t; cvta.to.shared.u64 t, %1; cvt.u32.u64 %0, t; }" : "=r"(a) : "l"(p));
  return a;
}
__device__ __forceinline__ void mma16h(float* d, const uint32_t* a, const uint32_t* b){
  asm volatile("mma.sync.aligned.m16n8k16.row.col.f32.f16.f16.f32 "
    "{%0,%1,%2,%3}, {%4,%5,%6,%7}, {%8,%9}, {%0,%1,%2,%3};\n"
    : "+f"(d[0]),"+f"(d[1]),"+f"(d[2]),"+f"(d[3])
    : "r"(a[0]),"r"(a[1]),"r"(a[2]),"r"(a[3]),
      "r"(b[0]),"r"(b[1]));
}
__device__ __forceinline__ void ldm_x4(uint32_t* r, uint32_t addr){
  asm volatile("ldmatrix.sync.aligned.m8n8.x4.shared.b16 {%0,%1,%2,%3}, [%4];"
    : "=r"(r[0]),"=r"(r[1]),"=r"(r[2]),"=r"(r[3]) : "r"(addr));
}
__device__ __forceinline__ void ldm_x4t(uint32_t* r, uint32_t addr){
  asm volatile("ldmatrix.sync.aligned.m8n8.x4.trans.shared.b16 {%0,%1,%2,%3}, [%4];"
    : "=r"(r[0]),"=r"(r[1]),"=r"(r[2]),"=r"(r[3]) : "r"(addr));
}
__device__ __forceinline__ void cp16(uint32_t smem, const void* g){
  asm volatile("cp.async.cg.shared.global [%0], [%1], 16;" :: "r"(smem), "l"(g));
}
#define CP_COMMIT() asm volatile("cp.async.commit_group;" ::: "memory")
#define CP_WAIT0()  asm volatile("cp.async.wait_group 0;" ::: "memory")
#define CP_WAIT1()  asm volatile("cp.async.wait_group 1;" ::: "memory")
#define CP_WAIT2()  asm volatile("cp.async.wait_group 2;" ::: "memory")

__device__ __forceinline__ uint32_t packh2(float x, float y){
  __half2 h = __floats2half2_rn(x, y);
  return *(uint32_t*)&h;
}

// ---------------- fused 2-value block reduction (blockDim.x == 256) ----------------
__device__ __forceinline__ float2 blockReduceSum2(float2 v, float2* sh){
  #pragma unroll
  for(int o=16;o>0;o>>=1){
    v.x += __shfl_xor_sync(0xffffffffu, v.x, o);
    v.y += __shfl_xor_sync(0xffffffffu, v.y, o);
  }
  int wid = threadIdx.x>>5;
  __syncthreads();
  if((threadIdx.x&31)==0) sh[wid]=v;
  __syncthreads();
  float2 r = sh[0];
  #pragma unroll
  for(int w=1;w<8;w++){ r.x += sh[w].x; r.y += sh[w].y; }
  return r;
}

// ---------------- merged fp32->fp16 conversion (single launch) ----------------
#define CN1 (NDEPTH*DIMM*3*DIMM/4)
#define CN2 (NDEPTH*DIMM*DIMM/4)
#define CN3 (NDEPTH*DIMM*FFD/4)
#define CN4 (NDEPTH*FFD*DIMM/4)
#define CN5 (NHEADS*SEQ*SEQ/4)
#define CNT (CN1+CN2+CN3+CN4+CN5)

__global__ void conv_all(const float* __restrict__ wq, const float* __restrict__ wo,
                         const float* __restrict__ w1, const float* __restrict__ w2,
                         const float* __restrict__ rp,
                         __half* __restrict__ dq, __half* __restrict__ dо_,
                         __half* __restrict__ d1, __half* __restrict__ d2,
                         __half* __restrict__ dr){
  int i = blockIdx.x*blockDim.x + threadIdx.x;
  const float* src; __half* dst; int off;
  if(i < CN1){ src=wq; dst=dq; off=i; }
  else if(i < CN1+CN2){ src=wo; dst=dо_; off=i-CN1; }
  else if(i < CN1+CN2+CN3){ src=w1; dst=d1; off=i-(CN1+CN2); }
  else if(i < CN1+CN2+CN3+CN4){ src=w2; dst=d2; off=i-(CN1+CN2+CN3); }
  else if(i < CNT){ src=rp; dst=dr; off=i-(CN1+CN2+CN3+CN4); }
  else return;
  float4 v = ((const float4*)src)[off];
  uint2 u;
  u.x = packh2(v.x, v.y);
  u.y = packh2(v.z, v.w);
  ((uint2*)dst)[off] = u;
}

// LayerNorm with single fused reduction pass (sum + sumsq together)
__global__ void layernorm_h(const float* __restrict__ x, const float* __restrict__ g,
                            const float* __restrict__ beta, __half* __restrict__ out){
  __shared__ float2 sh[8];
  int row = blockIdx.x, t = threadIdx.x;
  const float4* xr = (const float4*)(x + (size_t)row*DIMM);
  float4 v = xr[t];
  float2 acc;
  acc.x = v.x+v.y+v.z+v.w;
  acc.y = v.x*v.x + v.y*v.y + v.z*v.z + v.w*v.w;
  acc = blockReduceSum2(acc, sh);
  float mu = acc.x * (1.f/DIMM);
  float var = acc.y * (1.f/DIMM) - mu*mu;
  float rinv = rsqrtf(var + 1e-5f);
  const float4 gg = ((const float4*)g)[t];
  const float4 bb = ((const float4*)beta)[t];
  uint2 u;
  u.x = packh2((v.x-mu)*rinv*gg.x + bb.x, (v.y-mu)*rinv*gg.y + bb.y);
  u.y = packh2((v.z-mu)*rinv*gg.z + bb.z, (v.w-mu)*rinv*gg.w + bb.w);
  ((uint2*)(out + (size_t)row*DIMM))[t] = u;
}

// ---------------- fp16 GEMM: cp.async 4-stage pipeline, templated M-tile ----------------
#define APITCH 40
#define BPITCH 136
#define BSZ (32*BPITCH)
#define GH_SMEM_OF(BM) (4*((BM)*APITCH + BSZ)*2)

template<int EPI, typename OT, int BM>
__global__ void __launch_bounds__(256)
gemm_h(const __half* __restrict__ A, int lda,
       const __half* __restrict__ B, int ldb,
       OT* __restrict__ C, int ldc,
       const float* __restrict__ bias, const float* __restrict__ res,
       int M, int N, int K)
{
  constexpr int MT = BM/32;
  constexpr int NT = 4;
  constexpr int ASZ = BM*APITCH;
  constexpr int STG = ASZ+BSZ;
  constexpr int AIT = BM/64;
  extern __shared__ __half smh[];

  int t=threadIdx.x;
  const __half* Ag = A + (size_t)blockIdx.y*BM*lda;
  const __half* Bg = B + blockIdx.x*128;

  float acc[MT][NT][4];
  #pragma unroll
  for(int i=0;i<MT;i++)
    #pragma unroll
    for(int j=0;j<NT;j++)
      #pragma unroll
      for(int r=0;r<4;r++) acc[i][j][r]=0.f;

  int wid=t>>5, lane=t&31;
  int wm=wid>>2, wn=wid&3;
  int m0=wm*(16*MT), n0=wn*32;
  int qr=lane>>2, rr=lane&3;

  uint32_t sbase = smem_u32(smh);
  uint32_t aoff = sbase + (uint32_t)(((m0 + (lane&15))*APITCH + (lane>>4)*8) * 2);
  uint32_t boff = sbase + (uint32_t)((ASZ + (lane&15)*BPITCH + n0 + (lane>>4)*8) * 2);

  const int KT = K >> 5;

  auto load_tile = [&](int kt, int buf){
    __half* As = smh + buf*STG;
    __half* Bs = As + ASZ;
    const __half* Asrc = Ag + kt*32;
    #pragma unroll
    for(int i=0;i<AIT;i++){
      int c=t+256*i;
      cp16(smem_u32(As + (c>>2)*APITCH + ((c&3)<<3)),
           Asrc + (size_t)(c>>2)*lda + ((c&3)<<3));
    }
    const __half* Bsrc = Bg + (size_t)(kt*32)*ldb;
    #pragma unroll
    for(int i=0;i<2;i++){
      int c=t+256*i;
      cp16(smem_u32(Bs + (c>>4)*BPITCH + ((c&15)<<3)),
           Bsrc + (size_t)(c>>4)*ldb + ((c&15)<<3));
    }
  };

  #pragma unroll
  for(int s=0;s<3;s++){ load_tile(s,s); CP_COMMIT(); }

  for(int kt=0;kt<KT;kt++){
    CP_WAIT2();
    __syncthreads();
    if(kt+3<KT) load_tile(kt+3,(kt+3)&3);
    CP_COMMIT();
    uint32_t so = (uint32_t)(((kt&3)*STG)*2);
    #pragma unroll
    for(int ks=0;ks<2;ks++){
      uint32_t af[MT][4];
      #pragma unroll
      for(int mt=0;mt<MT;mt++)
        ldm_x4(af[mt], aoff + so + (uint32_t)((mt*16*APITCH + ks*16)*2));
      uint32_t bf[2][4];
      #pragma unroll
      for(int nh=0;nh<2;nh++)
        ldm_x4t(bf[nh], boff + so + (uint32_t)((ks*16*BPITCH + nh*16)*2));
      #pragma unroll
      for(int mt=0;mt<MT;mt++)
        #pragma unroll
        for(int nt=0;nt<NT;nt++)
          mma16h(acc[mt][nt], af[mt], &bf[nt>>1][(nt&1)*2]);
    }
  }

  int brow = blockIdx.y*BM + m0 + qr;
  int bcol = blockIdx.x*128 + n0 + (rr<<1);
  #pragma unroll
  for(int mt=0;mt<MT;mt++){
    #pragma unroll
    for(int nt=0;nt<NT;nt++){
      int col = bcol + nt*8;
      #pragma unroll
      for(int hh=0;hh<2;hh++){
        int row = brow + mt*16 + hh*8;
        float vx = acc[mt][nt][2*hh+0];
        float vy = acc[mt][nt][2*hh+1];
        if(EPI==1||EPI==2){ vx += bias[col]; vy += bias[col+1]; }
        if(EPI==2){
          vx = 0.5f*vx*(1.f+erff(vx*0.70710678118654752f));
          vy = 0.5f*vy*(1.f+erff(vy*0.70710678118654752f));
        }
        if(EPI==1){
          vx += res[(size_t)row*ldc+col];
          vy += res[(size_t)row*ldc+col+1];
        }
        if(sizeof(OT)==2){
          *(uint32_t*)((__half*)C + (size_t)row*ldc + col) = packh2(vx,vy);
        }else{
          float2 o; o.x=vx; o.y=vy;
          *(float2*)((float*)C + (size_t)row*ldc + col) = o;
        }
      }
    }
  }
}

// ---------------- fused flash attention (R8/R11 measured-best form) ----------------
#define FPITCH 72

__global__ void __launch_bounds__(128)
attn_flash_h(const __half* __restrict__ qkv, const __half* __restrict__ rpb,
             __half* __restrict__ O)
{
  __shared__ __half Qs[64*FPITCH];
  __shared__ __half Ks[2*64*FPITCH];
  __shared__ __half Vs[2*64*FPITCH];

  int t = threadIdx.x, lane = t&31, w = t>>5;
  int qr = lane>>2, rr = lane&3;
  int it = blockIdx.x, bh = blockIdx.y;
  int b = bh>>4, h = bh&15;
  const __half* Qg = qkv + (size_t)(b*SEQ + it*64)*(3*DIMM) + h*64;
  const __half* Kg = qkv + (size_t)b*SEQ*(3*DIMM) + DIMM   + h*64;
  const __half* Vg = qkv + (size_t)b*SEQ*(3*DIMM) + 2*DIMM + h*64;

  uint32_t sQ = smem_u32(Qs), sK = smem_u32(Ks), sV = smem_u32(Vs);

  #pragma unroll
  for(int u=0;u<4;u++){
    int c = t + 128*u;
    int row = c>>3, cc = c&7;
    cp16(sQ + (uint32_t)(row*FPITCH + cc*8)*2, Qg + (size_t)row*(3*DIMM) + cc*8);
  }
  #pragma unroll
  for(int u=0;u<8;u++){
    int c = t + 128*u;
    int mat = c>>9, row=(c>>3)&63, cc=c&7;
    const __half* src = (mat? Vg:Kg) + (size_t)row*(3*DIMM) + cc*8;
    uint32_t dst = (mat? sV:sK) + (uint32_t)(row*FPITCH + cc*8)*2;
    cp16(dst, src);
  }
  CP_COMMIT();
  #pragma unroll
  for(int u=0;u<8;u++){
    int c = t + 128*u;
    int mat = c>>9, row=(c>>3)&63, cc=c&7;
    const __half* src = (mat? Vg:Kg) + (size_t)(64+row)*(3*DIMM) + cc*8;
    uint32_t dst = (mat? sV:sK) + (uint32_t)(64*FPITCH + row*FPITCH + cc*8)*2;
    cp16(dst, src);
  }
  CP_COMMIT();

  int m0 = w*16;
  const __half* Rg = rpb + ((size_t)h*SEQ + it*64 + m0 + qr)*SEQ + 2*rr;

  uint32_t a_base  = sQ + (uint32_t)(((m0 + (lane&15))*FPITCH + (lane>>4)*8)*2);
  uint32_t k_lbase = (uint32_t)((((lane&7) + ((lane&16)?8:0))*FPITCH + ((lane&8)?8:0))*2);
  uint32_t v_lbase = (uint32_t)(((lane&15)*FPITCH + (lane>>4)*8)*2);

  uint32_t qf[4][4];
  float oacc[8][4];
  #pragma unroll
  for(int nf=0;nf<8;nf++)
    #pragma unroll
    for(int r=0;r<4;r++) oacc[nf][r]=0.f;
  float mrow0=-1e30f, mrow1=-1e30f, lrow0=0.f, lrow1=0.f;

  for(int jt=0;jt<16;jt++){
    if(jt<15) CP_WAIT1(); else CP_WAIT0();
    __syncthreads();
    if(jt==0){
      #pragma unroll
      for(int kb=0;kb<4;kb++) ldm_x4(qf[kb], a_base + (uint32_t)(kb*16*2));
    }
    uint32_t bufK = sK + (uint32_t)((jt&1)*64*FPITCH*2);
    uint32_t bufV = sV + (uint32_t)((jt&1)*64*FPITCH*2);

    uint32_t rpf[8][2];
    {
      const __half* rp = Rg + jt*64;
      #pragma unroll
      for(int nf=0;nf<8;nf++){
        rpf[nf][0] = *(const uint32_t*)(rp + nf*8);
        rpf[nf][1] = *(const uint32_t*)(rp + 8*SEQ + nf*8);
      }
    }

    float s[8][4];
    #pragma unroll
    for(int nf=0;nf<8;nf++)
      #pragma unroll
      for(int r=0;r<4;r++) s[nf][r]=0.f;
    #pragma unroll
    for(int kb=0;kb<4;kb++){
      #pragma unroll
      for(int jnp=0;jnp<4;jnp++){
        uint32_t kr[4];
        ldm_x4(kr, bufK + k_lbase + (uint32_t)((jnp*16*FPITCH + kb*16)*2));
        mma16h(s[2*jnp  ], qf[kb], kr);
        mma16h(s[2*jnp+1], qf[kb], kr+2);
      }
    }
    #pragma unroll
    for(int nf=0;nf<8;nf++){
      float2 r0 = __half22float2(*(__half2*)&rpf[nf][0]);
      float2 r1 = __half22float2(*(__half2*)&rpf[nf][1]);
      s[nf][0]=fmaf(s[nf][0],0.125f,r0.x);
      s[nf][1]=fmaf(s[nf][1],0.125f,r0.y);
      s[nf][2]=fmaf(s[nf][2],0.125f,r1.x);
      s[nf][3]=fmaf(s[nf][3],0.125f,r1.y);
    }
    float mx0=-1e30f, mx1=-1e30f;
    #pragma unroll
    for(int nf=0;nf<8;nf++){
      mx0=fmaxf(mx0,fmaxf(s[nf][0],s[nf][1]));
      mx1=fmaxf(mx1,fmaxf(s[nf][2],s[nf][3]));
    }
    mx0=fmaxf(mx0,__shfl_xor_sync(0xffffffffu,mx0,1));
    mx0=fmaxf(mx0,__shfl_xor_sync(0xffffffffu,mx0,2));
    mx1=fmaxf(mx1,__shfl_xor_sync(0xffffffffu,mx1,1));
    mx1=fmaxf(mx1,__shfl_xor_sync(0xffffffffu,mx1,2));
    float mn0=fmaxf(mrow0,mx0), mn1=fmaxf(mrow1,mx1);
    float a0=__expf(mrow0-mn0), a1=__expf(mrow1-mn1);
    mrow0=mn0; mrow1=mn1;
    float sum0=0.f, sum1=0.f;
    #pragma unroll
    for(int nf=0;nf<8;nf++){
      s[nf][0]=__expf(s[nf][0]-mn0); s[nf][1]=__expf(s[nf][1]-mn0);
      s[nf][2]=__expf(s[nf][2]-mn1); s[nf][3]=__expf(s[nf][3]-mn1);
      sum0 += s[nf][0]+s[nf][1];
      sum1 += s[nf][2]+s[nf][3];
    }
    sum0 += __shfl_xor_sync(0xffffffffu,sum0,1);
    sum0 += __shfl_xor_sync(0xffffffffu,sum0,2);
    sum1 += __shfl_xor_sync(0xffffffffu,sum1,1);
    sum1 += __shfl_xor_sync(0xffffffffu,sum1,2);
    lrow0 = lrow0*a0 + sum0;
    lrow1 = lrow1*a1 + sum1;
    #pragma unroll
    for(int nf=0;nf<8;nf++){
      oacc[nf][0]*=a0; oacc[nf][1]*=a0;
      oacc[nf][2]*=a1; oacc[nf][3]*=a1;
    }
    uint32_t pf[4][4];
    #pragma unroll
    for(int kb=0;kb<4;kb++){
      pf[kb][0]=packh2(s[2*kb  ][0], s[2*kb  ][1]);
      pf[kb][1]=packh2(s[2*kb  ][2], s[2*kb  ][3]);
      pf[kb][2]=packh2(s[2*kb+1][0], s[2*kb+1][1]);
      pf[kb][3]=packh2(s[2*kb+1][2], s[2*kb+1][3]);
    }
    #pragma unroll
    for(int kb=0;kb<4;kb++){
      #pragma unroll
      for(int nfp=0;nfp<4;nfp++){
        uint32_t vr[4];
        ldm_x4t(vr, bufV + v_lbase + (uint32_t)((kb*16*FPITCH + nfp*16)*2));
        mma16h(oacc[2*nfp  ], pf[kb], vr);
        mma16h(oacc[2*nfp+1], pf[kb], vr+2);
      }
    }
    __syncthreads();
    if(jt<14){
      int nt = jt+2, buf = jt&1;
      #pragma unroll
      for(int u=0;u<8;u++){
        int c = t + 128*u;
        int mat = c>>9, row=(c>>3)&63, cc=c&7;
        const __half* src = (mat? Vg:Kg) + (size_t)(nt*64+row)*(3*DIMM) + cc*8;
        uint32_t dst = (mat? sV:sK) + (uint32_t)(buf*64*FPITCH + row*FPITCH + cc*8)*2;
        cp16(dst, src);
      }
      CP_COMMIT();
    }
  }

  float inv0=1.f/lrow0, inv1=1.f/lrow1;
  __half* Ob = O + (size_t)(b*SEQ + it*64)*DIMM + h*64;
  #pragma unroll
  for(int nf=0;nf<8;nf++){
    *(uint32_t*)(Ob + (size_t)(m0+qr  )*DIMM + nf*8+2*rr) = packh2(oacc[nf][0]*inv0, oacc[nf][1]*inv0);
    *(uint32_t*)(Ob + (size_t)(m0+qr+8)*DIMM + nf*8+2*rr) = packh2(oacc[nf][2]*inv1, oacc[nf][3]*inv1);
  }
}

// ---------------- driver ----------------
extern "C" void kernel_launch(void* const* d_in, const int* in_sizes, int n_in,
                              void* d_out, int out_size){
  const float* x     =(const float*)d_in[0];
  const float* rpb   =(const float*)d_in[1];
  const float* ln1_g =(const float*)d_in[2];
  const float* ln1_b =(const float*)d_in[3];
  const float* w_qkv =(const float*)d_in[4];
  const float* w_out =(const float*)d_in[5];
  const float* b_out =(const float*)d_in[6];
  const float* ln2_g =(const float*)d_in[7];
  const float* ln2_b =(const float*)d_in[8];
  const float* w1    =(const float*)d_in[9];
  const float* b1    =(const float*)d_in[10];
  const float* w2    =(const float*)d_in[11];
  const float* b2    =(const float*)d_in[12];
  float* X = (float*)d_out;

  __half *hh, *qkvh, *oh, *ffh, *wqkvh, *wouth, *w1h, *w2h, *rpbh;
  cudaGetSymbolAddress((void**)&hh,    g_hh);
  cudaGetSymbolAddress((void**)&qkvh,  g_qkvh);
  cudaGetSymbolAddress((void**)&oh,    g_oh);
  cudaGetSymbolAddress((void**)&ffh,   g_ffh);
  cudaGetSymbolAddress((void**)&wqkvh, g_wqkvh);
  cudaGetSymbolAddress((void**)&wouth, g_wouth);
  cudaGetSymbolAddress((void**)&w1h,   g_w1h);
  cudaGetSymbolAddress((void**)&w2h,   g_w2h);
  cudaGetSymbolAddress((void**)&rpbh,  g_rpbh);

  cudaFuncSetAttribute((const void*)gemm_h<0,__half,128>, cudaFuncAttributeMaxDynamicSharedMemorySize, GH_SMEM_OF(128));
  cudaFuncSetAttribute((const void*)gemm_h<2,__half,128>, cudaFuncAttributeMaxDynamicSharedMemorySize, GH_SMEM_OF(128));
  cudaFuncSetAttribute((const void*)gemm_h<1,float,64>,   cudaFuncAttributeMaxDynamicSharedMemorySize, GH_SMEM_OF(64));

  conv_all<<<(CNT+255)/256, 256>>>(w_qkv, w_out, w1, w2, rpb,
                                   wqkvh, wouth, w1h, w2h, rpbh);

  for(int l=0;l<NDEPTH;l++){
    const float* Xin = (l==0) ? x : X;
    // ---- attention block ----
    layernorm_h<<<NTOK,256>>>(Xin, ln1_g + l*DIMM, ln1_b + l*DIMM, hh);
    gemm_h<0,__half,128><<<dim3(24,16),256,GH_SMEM_OF(128)>>>(
        hh, DIMM, wqkvh + (size_t)l*DIMM*3*DIMM, 3*DIMM,
        qkvh, 3*DIMM, nullptr, nullptr, NTOK, 3*DIMM, DIMM);
    attn_flash_h<<<dim3(16,NBATCH*NHEADS),128>>>(qkvh, rpbh, oh);
    gemm_h<1,float,64><<<dim3(8,32),256,GH_SMEM_OF(64)>>>(
        oh, DIMM, wouth + (size_t)l*DIMM*DIMM, DIMM,
        X, DIMM, b_out + l*DIMM, Xin, NTOK, DIMM, DIMM);
    // ---- FFN block ----
    layernorm_h<<<NTOK,256>>>(X, ln2_g + l*DIMM, ln2_b + l*DIMM, hh);
    gemm_h<2,__half,128><<<dim3(32,16),256,GH_SMEM_OF(128)>>>(
        hh, DIMM, w1h + (size_t)l*DIMM*FFD, FFD,
        ffh, FFD, b1 + l*FFD, nullptr, NTOK, FFD, DIMM);
    gemm_h<1,float,64><<<dim3(8,32),256,GH_SMEM_OF(64)>>>(
        ffh, FFD, w2h + (size_t)l*FFD*DIMM, DIMM,
        X, DIMM, b2 + l*DIMM, X, NTOK, DIMM, FFD);
  }
}

// round 14
// speedup vs baseline: 1.0426x; 1.0389x over previous
#include <cuda_runtime.h>
#include <cuda_fp16.h>
#include <math.h>
#include <stdint.h>

#define SEQ    1024
#define DIMM   1024
#define NHEADS 16
#define FFD    4096
#define NBATCH 2
#define NTOK   (NBATCH*SEQ)
#define NDEPTH 6

// ---------------- scratch (allocation-free: __device__ globals) ----------------
__device__ __half g_hh[NTOK*DIMM];
__device__ __half g_qkvh[NTOK*3*DIMM];
__device__ __half g_oh[NTOK*DIMM];
__device__ __half g_ffh[NTOK*FFD];
__device__ __half g_wqkvh[(size_t)NDEPTH*DIMM*3*DIMM];
__device__ __half g_wouth[(size_t)NDEPTH*DIMM*DIMM];
__device__ __half g_w1h[(size_t)NDEPTH*DIMM*FFD];
__device__ __half g_w2h[(size_t)NDEPTH*FFD*DIMM];
__device__ __half g_rpbh[(size_t)NHEADS*SEQ*SEQ];

// ---------------- ptx helpers ----------------
__device__ __forceinline__ uint32_t smem_u32(const void* p){
  uint32_t a;
  asm("{ .reg .u64 t; cvta.to.shared.u64 t, %1; cvt.u32.u64 %0, t; }" : "=r"(a) : "l"(p));
  return a;
}
__device__ __forceinline__ void mma16h(float* d, const uint32_t* a, const uint32_t* b){
  asm volatile("mma.sync.aligned.m16n8k16.row.col.f32.f16.f16.f32 "
    "{%0,%1,%2,%3}, {%4,%5,%6,%7}, {%8,%9}, {%0,%1,%2,%3};\n"
    : "+f"(d[0]),"+f"(d[1]),"+f"(d[2]),"+f"(d[3])
    : "r"(a[0]),"r"(a[1]),"r"(a[2]),"r"(a[3]),
      "r"(b[0]),"r"(b[1]));
}
__device__ __forceinline__ void ldm_x4(uint32_t* r, uint32_t addr){
  asm volatile("ldmatrix.sync.aligned.m8n8.x4.shared.b16 {%0,%1,%2,%3}, [%4];"
    : "=r"(r[0]),"=r"(r[1]),"=r"(r[2]),"=r"(r[3]) : "r"(addr));
}
__device__ __forceinline__ void ldm_x4t(uint32_t* r, uint32_t addr){
  asm volatile("ldmatrix.sync.aligned.m8n8.x4.trans.shared.b16 {%0,%1,%2,%3}, [%4];"
    : "=r"(r[0]),"=r"(r[1]),"=r"(r[2]),"=r"(r[3]) : "r"(addr));
}
__device__ __forceinline__ void cp16(uint32_t smem, const void* g){
  asm volatile("cp.async.cg.shared.global [%0], [%1], 16;" :: "r"(smem), "l"(g));
}
#define CP_COMMIT() asm volatile("cp.async.commit_group;" ::: "memory")
#define CP_WAIT0()  asm volatile("cp.async.wait_group 0;" ::: "memory")
#define CP_WAIT1()  asm volatile("cp.async.wait_group 1;" ::: "memory")

__device__ __forceinline__ uint32_t packh2(float x, float y){
  __half2 h = __floats2half2_rn(x, y);
  return *(uint32_t*)&h;
}

// ---------------- block reduction (blockDim.x == 256) ----------------
__device__ __forceinline__ float blockReduceSum(float val, float* sh){
  #pragma unroll
  for(int o=16;o>0;o>>=1) val += __shfl_xor_sync(0xffffffffu, val, o);
  int wid = threadIdx.x>>5;
  __syncthreads();
  if((threadIdx.x&31)==0) sh[wid]=val;
  __syncthreads();
  float r = 0.f;
  #pragma unroll
  for(int w=0;w<8;w++) r += sh[w];
  return r;
}

// ---------------- merged fp32->fp16 conversion (single launch) ----------------
#define CN1 (NDEPTH*DIMM*3*DIMM/4)
#define CN2 (NDEPTH*DIMM*DIMM/4)
#define CN3 (NDEPTH*DIMM*FFD/4)
#define CN4 (NDEPTH*FFD*DIMM/4)
#define CN5 (NHEADS*SEQ*SEQ/4)
#define CNT (CN1+CN2+CN3+CN4+CN5)

__global__ void conv_all(const float* __restrict__ wq, const float* __restrict__ wo,
                         const float* __restrict__ w1, const float* __restrict__ w2,
                         const float* __restrict__ rp,
                         __half* __restrict__ dq, __half* __restrict__ dо_,
                         __half* __restrict__ d1, __half* __restrict__ d2,
                         __half* __restrict__ dr){
  int i = blockIdx.x*blockDim.x + threadIdx.x;
  const float* src; __half* dst; int off;
  if(i < CN1){ src=wq; dst=dq; off=i; }
  else if(i < CN1+CN2){ src=wo; dst=dо_; off=i-CN1; }
  else if(i < CN1+CN2+CN3){ src=w1; dst=d1; off=i-(CN1+CN2); }
  else if(i < CN1+CN2+CN3+CN4){ src=w2; dst=d2; off=i-(CN1+CN2+CN3); }
  else if(i < CNT){ src=rp; dst=dr; off=i-(CN1+CN2+CN3+CN4); }
  else return;
  float4 v = ((const float4*)src)[off];
  uint2 u;
  u.x = packh2(v.x, v.y);
  u.y = packh2(v.z, v.w);
  ((uint2*)dst)[off] = u;
}

// LayerNorm (R11 two-pass measured-best form)
__global__ void layernorm_h(const float* __restrict__ x, const float* __restrict__ g,
                            const float* __restrict__ beta, __half* __restrict__ out){
  __shared__ float sh[8];
  int row = blockIdx.x, t = threadIdx.x;
  const float4* xr = (const float4*)(x + (size_t)row*DIMM);
  float4 v = xr[t];
  float s = v.x+v.y+v.z+v.w;
  s = blockReduceSum(s, sh);
  float mu = s * (1.f/DIMM);
  float dx=v.x-mu, dy=v.y-mu, dz=v.z-mu, dw=v.w-mu;
  float ss = dx*dx+dy*dy+dz*dz+dw*dw;
  ss = blockReduceSum(ss, sh);
  float rinv = rsqrtf(ss*(1.f/DIMM) + 1e-5f);
  const float4 gg = ((const float4*)g)[t];
  const float4 bb = ((const float4*)beta)[t];
  uint2 u;
  u.x = packh2(dx*rinv*gg.x + bb.x, dy*rinv*gg.y + bb.y);
  u.y = packh2(dz*rinv*gg.z + bb.z, dw*rinv*gg.w + bb.w);
  ((uint2*)(out + (size_t)row*DIMM))[t] = u;
}

// ---------------- fp16 GEMM: BK=64, 3-stage cp.async pipeline ----------------
// Half the pipeline turns (barriers/waits) of the BK=32 version; identical
// total cp.async / ldmatrix / mma work.
#define APITCH 72           // 64 halves + 8 pad (144B rows: conflict-free ldmatrix)
#define BPITCH 136
#define BSZ (64*BPITCH)     // 64 k-rows x 128 n
#define GH_SMEM_OF(BM) (3*((BM)*APITCH + BSZ)*2)

template<int EPI, typename OT, int BM>
__global__ void __launch_bounds__(256)
gemm_h(const __half* __restrict__ A, int lda,
       const __half* __restrict__ B, int ldb,
       OT* __restrict__ C, int ldc,
       const float* __restrict__ bias, const float* __restrict__ res,
       int M, int N, int K)
{
  constexpr int MT = BM/32;          // 4 for BM=128, 2 for BM=64
  constexpr int NT = 4;
  constexpr int ASZ = BM*APITCH;
  constexpr int STG = ASZ+BSZ;
  constexpr int AIT = BM/32;         // A cp16s per thread (BM*8/256)
  extern __shared__ __half smh[];

  int t=threadIdx.x;
  const __half* Ag = A + (size_t)blockIdx.y*BM*lda;
  const __half* Bg = B + blockIdx.x*128;

  float acc[MT][NT][4];
  #pragma unroll
  for(int i=0;i<MT;i++)
    #pragma unroll
    for(int j=0;j<NT;j++)
      #pragma unroll
      for(int r=0;r<4;r++) acc[i][j][r]=0.f;

  int wid=t>>5, lane=t&31;
  int wm=wid>>2, wn=wid&3;
  int m0=wm*(16*MT), n0=wn*32;
  int qr=lane>>2, rr=lane&3;

  uint32_t sbase = smem_u32(smh);
  uint32_t aoff = sbase + (uint32_t)(((m0 + (lane&15))*APITCH + (lane>>4)*8) * 2);
  uint32_t boff = sbase + (uint32_t)((ASZ + (lane&15)*BPITCH + n0 + (lane>>4)*8) * 2);

  const int KT = K >> 6;             // BK=64 tiles

  auto load_tile = [&](int kt, int buf){
    __half* As = smh + buf*STG;
    __half* Bs = As + ASZ;
    const __half* Asrc = Ag + kt*64;
    #pragma unroll
    for(int i=0;i<AIT;i++){
      int c=t+256*i;                  // 0 .. BM*8-1
      cp16(smem_u32(As + (c>>3)*APITCH + ((c&7)<<3)),
           Asrc + (size_t)(c>>3)*lda + ((c&7)<<3));
    }
    const __half* Bsrc = Bg + (size_t)(kt*64)*ldb;
    #pragma unroll
    for(int i=0;i<4;i++){
      int c=t+256*i;                  // 0 .. 1023 (64 rows x 16 chunks)
      cp16(smem_u32(Bs + (c>>4)*BPITCH + ((c&15)<<3)),
           Bsrc + (size_t)(c>>4)*ldb + ((c&15)<<3));
    }
  };

  // prologue: tiles 0,1
  load_tile(0,0); CP_COMMIT();
  load_tile(1,1); CP_COMMIT();

  for(int kt=0;kt<KT;kt++){
    CP_WAIT1();
    __syncthreads();
    if(kt+2<KT) load_tile(kt+2,(kt+2)%3);
    CP_COMMIT();                       // empty groups in tail keep count stable
    uint32_t so = (uint32_t)(((kt%3)*STG)*2);
    #pragma unroll
    for(int ks=0;ks<4;ks++){
      uint32_t af[MT][4];
      #pragma unroll
      for(int mt=0;mt<MT;mt++)
        ldm_x4(af[mt], aoff + so + (uint32_t)((mt*16*APITCH + ks*16)*2));
      uint32_t bf[2][4];
      #pragma unroll
      for(int nh=0;nh<2;nh++)
        ldm_x4t(bf[nh], boff + so + (uint32_t)((ks*16*BPITCH + nh*16)*2));
      #pragma unroll
      for(int mt=0;mt<MT;mt++)
        #pragma unroll
        for(int nt=0;nt<NT;nt++)
          mma16h(acc[mt][nt], af[mt], &bf[nt>>1][(nt&1)*2]);
    }
  }

  int brow = blockIdx.y*BM + m0 + qr;
  int bcol = blockIdx.x*128 + n0 + (rr<<1);
  #pragma unroll
  for(int mt=0;mt<MT;mt++){
    #pragma unroll
    for(int nt=0;nt<NT;nt++){
      int col = bcol + nt*8;
      #pragma unroll
      for(int hh=0;hh<2;hh++){
        int row = brow + mt*16 + hh*8;
        float vx = acc[mt][nt][2*hh+0];
        float vy = acc[mt][nt][2*hh+1];
        if(EPI==1||EPI==2){ vx += bias[col]; vy += bias[col+1]; }
        if(EPI==2){
          vx = 0.5f*vx*(1.f+erff(vx*0.70710678118654752f));
          vy = 0.5f*vy*(1.f+erff(vy*0.70710678118654752f));
        }
        if(EPI==1){
          vx += res[(size_t)row*ldc+col];
          vy += res[(size_t)row*ldc+col+1];
        }
        if(sizeof(OT)==2){
          *(uint32_t*)((__half*)C + (size_t)row*ldc + col) = packh2(vx,vy);
        }else{
          float2 o; o.x=vx; o.y=vy;
          *(float2*)((float*)C + (size_t)row*ldc + col) = o;
        }
      }
    }
  }
}

// ---------------- fused flash attention (R8/R11 measured-best form) ----------------
#define FPITCH 72

__global__ void __launch_bounds__(128)
attn_flash_h(const __half* __restrict__ qkv, const __half* __restrict__ rpb,
             __half* __restrict__ O)
{
  __shared__ __half Qs[64*FPITCH];
  __shared__ __half Ks[2*64*FPITCH];
  __shared__ __half Vs[2*64*FPITCH];

  int t = threadIdx.x, lane = t&31, w = t>>5;
  int qr = lane>>2, rr = lane&3;
  int it = blockIdx.x, bh = blockIdx.y;
  int b = bh>>4, h = bh&15;
  const __half* Qg = qkv + (size_t)(b*SEQ + it*64)*(3*DIMM) + h*64;
  const __half* Kg = qkv + (size_t)b*SEQ*(3*DIMM) + DIMM   + h*64;
  const __half* Vg = qkv + (size_t)b*SEQ*(3*DIMM) + 2*DIMM + h*64;

  uint32_t sQ = smem_u32(Qs), sK = smem_u32(Ks), sV = smem_u32(Vs);

  #pragma unroll
  for(int u=0;u<4;u++){
    int c = t + 128*u;
    int row = c>>3, cc = c&7;
    cp16(sQ + (uint32_t)(row*FPITCH + cc*8)*2, Qg + (size_t)row*(3*DIMM) + cc*8);
  }
  #pragma unroll
  for(int u=0;u<8;u++){
    int c = t + 128*u;
    int mat = c>>9, row=(c>>3)&63, cc=c&7;
    const __half* src = (mat? Vg:Kg) + (size_t)row*(3*DIMM) + cc*8;
    uint32_t dst = (mat? sV:sK) + (uint32_t)(row*FPITCH + cc*8)*2;
    cp16(dst, src);
  }
  CP_COMMIT();
  #pragma unroll
  for(int u=0;u<8;u++){
    int c = t + 128*u;
    int mat = c>>9, row=(c>>3)&63, cc=c&7;
    const __half* src = (mat? Vg:Kg) + (size_t)(64+row)*(3*DIMM) + cc*8;
    uint32_t dst = (mat? sV:sK) + (uint32_t)(64*FPITCH + row*FPITCH + cc*8)*2;
    cp16(dst, src);
  }
  CP_COMMIT();

  int m0 = w*16;
  const __half* Rg = rpb + ((size_t)h*SEQ + it*64 + m0 + qr)*SEQ + 2*rr;

  uint32_t a_base  = sQ + (uint32_t)(((m0 + (lane&15))*FPITCH + (lane>>4)*8)*2);
  uint32_t k_lbase = (uint32_t)((((lane&7) + ((lane&16)?8:0))*FPITCH + ((lane&8)?8:0))*2);
  uint32_t v_lbase = (uint32_t)(((lane&15)*FPITCH + (lane>>4)*8)*2);

  uint32_t qf[4][4];
  float oacc[8][4];
  #pragma unroll
  for(int nf=0;nf<8;nf++)
    #pragma unroll
    for(int r=0;r<4;r++) oacc[nf][r]=0.f;
  float mrow0=-1e30f, mrow1=-1e30f, lrow0=0.f, lrow1=0.f;

  for(int jt=0;jt<16;jt++){
    if(jt<15) CP_WAIT1(); else CP_WAIT0();
    __syncthreads();
    if(jt==0){
      #pragma unroll
      for(int kb=0;kb<4;kb++) ldm_x4(qf[kb], a_base + (uint32_t)(kb*16*2));
    }
    uint32_t bufK = sK + (uint32_t)((jt&1)*64*FPITCH*2);
    uint32_t bufV = sV + (uint32_t)((jt&1)*64*FPITCH*2);

    uint32_t rpf[8][2];
    {
      const __half* rp = Rg + jt*64;
      #pragma unroll
      for(int nf=0;nf<8;nf++){
        rpf[nf][0] = *(const uint32_t*)(rp + nf*8);
        rpf[nf][1] = *(const uint32_t*)(rp + 8*SEQ + nf*8);
      }
    }

    float s[8][4];
    #pragma unroll
    for(int nf=0;nf<8;nf++)
      #pragma unroll
      for(int r=0;r<4;r++) s[nf][r]=0.f;
    #pragma unroll
    for(int kb=0;kb<4;kb++){
      #pragma unroll
      for(int jnp=0;jnp<4;jnp++){
        uint32_t kr[4];
        ldm_x4(kr, bufK + k_lbase + (uint32_t)((jnp*16*FPITCH + kb*16)*2));
        mma16h(s[2*jnp  ], qf[kb], kr);
        mma16h(s[2*jnp+1], qf[kb], kr+2);
      }
    }
    #pragma unroll
    for(int nf=0;nf<8;nf++){
      float2 r0 = __half22float2(*(__half2*)&rpf[nf][0]);
      float2 r1 = __half22float2(*(__half2*)&rpf[nf][1]);
      s[nf][0]=fmaf(s[nf][0],0.125f,r0.x);
      s[nf][1]=fmaf(s[nf][1],0.125f,r0.y);
      s[nf][2]=fmaf(s[nf][2],0.125f,r1.x);
      s[nf][3]=fmaf(s[nf][3],0.125f,r1.y);
    }
    float mx0=-1e30f, mx1=-1e30f;
    #pragma unroll
    for(int nf=0;nf<8;nf++){
      mx0=fmaxf(mx0,fmaxf(s[nf][0],s[nf][1]));
      mx1=fmaxf(mx1,fmaxf(s[nf][2],s[nf][3]));
    }
    mx0=fmaxf(mx0,__shfl_xor_sync(0xffffffffu,mx0,1));
    mx0=fmaxf(mx0,__shfl_xor_sync(0xffffffffu,mx0,2));
    mx1=fmaxf(mx1,__shfl_xor_sync(0xffffffffu,mx1,1));
    mx1=fmaxf(mx1,__shfl_xor_sync(0xffffffffu,mx1,2));
    float mn0=fmaxf(mrow0,mx0), mn1=fmaxf(mrow1,mx1);
    float a0=__expf(mrow0-mn0), a1=__expf(mrow1-mn1);
    mrow0=mn0; mrow1=mn1;
    float sum0=0.f, sum1=0.f;
    #pragma unroll
    for(int nf=0;nf<8;nf++){
      s[nf][0]=__expf(s[nf][0]-mn0); s[nf][1]=__expf(s[nf][1]-mn0);
      s[nf][2]=__expf(s[nf][2]-mn1); s[nf][3]=__expf(s[nf][3]-mn1);
      sum0 += s[nf][0]+s[nf][1];
      sum1 += s[nf][2]+s[nf][3];
    }
    sum0 += __shfl_xor_sync(0xffffffffu,sum0,1);
    sum0 += __shfl_xor_sync(0xffffffffu,sum0,2);
    sum1 += __shfl_xor_sync(0xffffffffu,sum1,1);
    sum1 += __shfl_xor_sync(0xffffffffu,sum1,2);
    lrow0 = lrow0*a0 + sum0;
    lrow1 = lrow1*a1 + sum1;
    #pragma unroll
    for(int nf=0;nf<8;nf++){
      oacc[nf][0]*=a0; oacc[nf][1]*=a0;
      oacc[nf][2]*=a1; oacc[nf][3]*=a1;
    }
    uint32_t pf[4][4];
    #pragma unroll
    for(int kb=0;kb<4;kb++){
      pf[kb][0]=packh2(s[2*kb  ][0], s[2*kb  ][1]);
      pf[kb][1]=packh2(s[2*kb  ][2], s[2*kb  ][3]);
      pf[kb][2]=packh2(s[2*kb+1][0], s[2*kb+1][1]);
      pf[kb][3]=packh2(s[2*kb+1][2], s[2*kb+1][3]);
    }
    #pragma unroll
    for(int kb=0;kb<4;kb++){
      #pragma unroll
      for(int nfp=0;nfp<4;nfp++){
        uint32_t vr[4];
        ldm_x4t(vr, bufV + v_lbase + (uint32_t)((kb*16*FPITCH + nfp*16)*2));
        mma16h(oacc[2*nfp  ], pf[kb], vr);
        mma16h(oacc[2*nfp+1], pf[kb], vr+2);
      }
    }
    __syncthreads();
    if(jt<14){
      int nt = jt+2, buf = jt&1;
      #pragma unroll
      for(int u=0;u<8;u++){
        int c = t + 128*u;
        int mat = c>>9, row=(c>>3)&63, cc=c&7;
        const __half* src = (mat? Vg:Kg) + (size_t)(nt*64+row)*(3*DIMM) + cc*8;
        uint32_t dst = (mat? sV:sK) + (uint32_t)(buf*64*FPITCH + row*FPITCH + cc*8)*2;
        cp16(dst, src);
      }
      CP_COMMIT();
    }
  }

  float inv0=1.f/lrow0, inv1=1.f/lrow1;
  __half* Ob = O + (size_t)(b*SEQ + it*64)*DIMM + h*64;
  #pragma unroll
  for(int nf=0;nf<8;nf++){
    *(uint32_t*)(Ob + (size_t)(m0+qr  )*DIMM + nf*8+2*rr) = packh2(oacc[nf][0]*inv0, oacc[nf][1]*inv0);
    *(uint32_t*)(Ob + (size_t)(m0+qr+8)*DIMM + nf*8+2*rr) = packh2(oacc[nf][2]*inv1, oacc[nf][3]*inv1);
  }
}

// ---------------- driver ----------------
extern "C" void kernel_launch(void* const* d_in, const int* in_sizes, int n_in,
                              void* d_out, int out_size){
  const float* x     =(const float*)d_in[0];
  const float* rpb   =(const float*)d_in[1];
  const float* ln1_g =(const float*)d_in[2];
  const float* ln1_b =(const float*)d_in[3];
  const float* w_qkv =(const float*)d_in[4];
  const float* w_out =(const float*)d_in[5];
  const float* b_out =(const float*)d_in[6];
  const float* ln2_g =(const float*)d_in[7];
  const float* ln2_b =(const float*)d_in[8];
  const float* w1    =(const float*)d_in[9];
  const float* b1    =(const float*)d_in[10];
  const float* w2    =(const float*)d_in[11];
  const float* b2    =(const float*)d_in[12];
  float* X = (float*)d_out;

  __half *hh, *qkvh, *oh, *ffh, *wqkvh, *wouth, *w1h, *w2h, *rpbh;
  cudaGetSymbolAddress((void**)&hh,    g_hh);
  cudaGetSymbolAddress((void**)&qkvh,  g_qkvh);
  cudaGetSymbolAddress((void**)&oh,    g_oh);
  cudaGetSymbolAddress((void**)&ffh,   g_ffh);
  cudaGetSymbolAddress((void**)&wqkvh, g_wqkvh);
  cudaGetSymbolAddress((void**)&wouth, g_wouth);
  cudaGetSymbolAddress((void**)&w1h,   g_w1h);
  cudaGetSymbolAddress((void**)&w2h,   g_w2h);
  cudaGetSymbolAddress((void**)&rpbh,  g_rpbh);

  cudaFuncSetAttribute((const void*)gemm_h<0,__half,128>, cudaFuncAttributeMaxDynamicSharedMemorySize, GH_SMEM_OF(128));
  cudaFuncSetAttribute((const void*)gemm_h<2,__half,128>, cudaFuncAttributeMaxDynamicSharedMemorySize, GH_SMEM_OF(128));
  cudaFuncSetAttribute((const void*)gemm_h<1,float,64>,   cudaFuncAttributeMaxDynamicSharedMemorySize, GH_SMEM_OF(64));

  conv_all<<<(CNT+255)/256, 256>>>(w_qkv, w_out, w1, w2, rpb,
                                   wqkvh, wouth, w1h, w2h, rpbh);

  for(int l=0;l<NDEPTH;l++){
    const float* Xin = (l==0) ? x : X;
    // ---- attention block ----
    layernorm_h<<<NTOK,256>>>(Xin, ln1_g + l*DIMM, ln1_b + l*DIMM, hh);
    gemm_h<0,__half,128><<<dim3(24,16),256,GH_SMEM_OF(128)>>>(
        hh, DIMM, wqkvh + (size_t)l*DIMM*3*DIMM, 3*DIMM,
        qkvh, 3*DIMM, nullptr, nullptr, NTOK, 3*DIMM, DIMM);
    attn_flash_h<<<dim3(16,NBATCH*NHEADS),128>>>(qkvh, rpbh, oh);
    gemm_h<1,float,64><<<dim3(8,32),256,GH_SMEM_OF(64)>>>(
        oh, DIMM, wouth + (size_t)l*DIMM*DIMM, DIMM,
        X, DIMM, b_out + l*DIMM, Xin, NTOK, DIMM, DIMM);
    // ---- FFN block ----
    layernorm_h<<<NTOK,256>>>(X, ln2_g + l*DIMM, ln2_b + l*DIMM, hh);
    gemm_h<2,__half,128><<<dim3(32,16),256,GH_SMEM_OF(128)>>>(
        hh, DIMM, w1h + (size_t)l*DIMM*FFD, FFD,
        ffh, FFD, b1 + l*FFD, nullptr, NTOK, FFD, DIMM);
    gemm_h<1,float,64><<<dim3(8,32),256,GH_SMEM_OF(64)>>>(
        ffh, FFD, w2h + (size_t)l*FFD*DIMM, DIMM,
        X, DIMM, b2 + l*DIMM, X, NTOK, DIMM, FFD);
  }
}